// round 1
// baseline (speedup 1.0000x reference)
#include <cuda_runtime.h>
#include <math.h>

// Problem constants (fixed by the reference)
#define B_  8
#define T_  64
#define N_  170
#define C_  128
#define H_  8
#define D_  16
#define BT_ (B_*T_)          // 512
#define M_  (BT_*N_)         // 87040 rows (multiple of 64)

// Scratch (allocation-free rule: __device__ globals)
__device__ float g_q [M_*C_];
__device__ float g_k [M_*C_];
__device__ float g_v [M_*C_];
__device__ float g_ao[M_*C_];

// ---------------------------------------------------------------------------
// GEMM: out[M,128] = A[M,128] @ W^T + bias      (torch Linear semantics)
// BM=64 rows per block, full N=K=128. 256 threads, 4x8 register tile.
// Smem: As[64][132] (padded), Ws[128][132] holding W transposed (Wt[k][c]).
// ---------------------------------------------------------------------------
#define GBM 64
#define APAD 132

__global__ __launch_bounds__(256, 2)
void gemm128(const float* __restrict__ A, const float* __restrict__ W,
             const float* __restrict__ bias, float* __restrict__ out)
{
    extern __shared__ float sm[];
    float* As = sm;                    // 64 * 132
    float* Ws = sm + GBM * APAD;       // 128 * 132 : Ws[k*APAD + c] = W[c][k]

    const int tid  = threadIdx.x;
    const int row0 = blockIdx.x * GBM;

    // Load A tile: 64x128 floats = 2048 float4, coalesced
    {
        const float4* Ag = (const float4*)(A + (size_t)row0 * C_);
        #pragma unroll
        for (int i = 0; i < 8; i++) {
            int idx4 = tid + i * 256;          // 0..2047
            int r  = idx4 >> 5;                // row 0..63
            int c4 = idx4 & 31;                // float4 col 0..31
            *(float4*)&As[r * APAD + c4 * 4] = Ag[idx4];
        }
    }
    // Load W transposed: read coalesced, scatter into Ws[k][c]
    {
        #pragma unroll
        for (int i = 0; i < 16; i++) {
            int idx4 = tid + i * 256;          // 0..4095
            int c  = idx4 >> 5;                // W row (output channel)
            int k4 = (idx4 & 31) * 4;
            float4 w = ((const float4*)W)[idx4];
            Ws[(k4 + 0) * APAD + c] = w.x;
            Ws[(k4 + 1) * APAD + c] = w.y;
            Ws[(k4 + 2) * APAD + c] = w.z;
            Ws[(k4 + 3) * APAD + c] = w.w;
        }
    }
    __syncthreads();

    const int ty = tid >> 4;    // 0..15 -> rows ty*4 .. ty*4+3
    const int tx = tid & 15;    // cols tx*8 .. tx*8+7

    float acc[4][8];
    #pragma unroll
    for (int m = 0; m < 4; m++)
        #pragma unroll
        for (int n = 0; n < 8; n++) acc[m][n] = 0.f;

    #pragma unroll 8
    for (int k = 0; k < C_; k++) {
        float a0 = As[(ty * 4 + 0) * APAD + k];
        float a1 = As[(ty * 4 + 1) * APAD + k];
        float a2 = As[(ty * 4 + 2) * APAD + k];
        float a3 = As[(ty * 4 + 3) * APAD + k];
        float4 b0 = *(float4*)&Ws[k * APAD + tx * 8];
        float4 b1 = *(float4*)&Ws[k * APAD + tx * 8 + 4];
        float bb[8] = {b0.x, b0.y, b0.z, b0.w, b1.x, b1.y, b1.z, b1.w};
        float aa[4] = {a0, a1, a2, a3};
        #pragma unroll
        for (int m = 0; m < 4; m++)
            #pragma unroll
            for (int n = 0; n < 8; n++)
                acc[m][n] = fmaf(aa[m], bb[n], acc[m][n]);
    }

    float4 bb0 = *(const float4*)&bias[tx * 8];
    float4 bb1 = *(const float4*)&bias[tx * 8 + 4];
    #pragma unroll
    for (int m = 0; m < 4; m++) {
        float* orow = out + (size_t)(row0 + ty * 4 + m) * C_ + tx * 8;
        float4 r0 = make_float4(acc[m][0] + bb0.x, acc[m][1] + bb0.y,
                                acc[m][2] + bb0.z, acc[m][3] + bb0.w);
        float4 r1 = make_float4(acc[m][4] + bb1.x, acc[m][5] + bb1.y,
                                acc[m][6] + bb1.z, acc[m][7] + bb1.w);
        *(float4*)orow       = r0;
        *(float4*)(orow + 4) = r1;
    }
}

// ---------------------------------------------------------------------------
// Attention: one block per (bt, h). K,V head tiles (170x16) staged in smem.
// One thread per query row, online softmax, FP32 throughout.
// out[btqhd] = softmax_k(q.k / sqrt(C)) @ v
// ---------------------------------------------------------------------------
__global__ __launch_bounds__(256)
void attn_kernel(const float* __restrict__ q, const float* __restrict__ k,
                 const float* __restrict__ v, float* __restrict__ ao)
{
    __shared__ float ks[N_ * D_];   // 10880 B
    __shared__ float vs[N_ * D_];

    const int bt  = blockIdx.x;
    const int h   = blockIdx.y;
    const int tid = threadIdx.x;
    const size_t base = (size_t)bt * N_ * C_ + h * D_;

    for (int idx = tid; idx < N_ * D_; idx += 256) {
        int n = idx >> 4, d = idx & 15;
        ks[idx] = k[base + (size_t)n * C_ + d];
        vs[idx] = v[base + (size_t)n * C_ + d];
    }
    __syncthreads();

    if (tid < N_) {
        const float4* qp = (const float4*)&q[base + (size_t)tid * C_];
        float4 q0 = qp[0], q1 = qp[1], q2 = qp[2], q3 = qp[3];

        const float scale = 0.08838834764831845f;   // 1/sqrt(128)
        float m = -1e30f, l = 0.f;
        float4 o0 = make_float4(0,0,0,0), o1 = o0, o2 = o0, o3 = o0;

        for (int j = 0; j < N_; j++) {
            const float4* kr = (const float4*)&ks[j * D_];
            float4 k0 = kr[0], k1 = kr[1], k2 = kr[2], k3 = kr[3];
            float s0 = q0.x*k0.x + q0.y*k0.y + q0.z*k0.z + q0.w*k0.w;
            float s1 = q1.x*k1.x + q1.y*k1.y + q1.z*k1.z + q1.w*k1.w;
            float s2 = q2.x*k2.x + q2.y*k2.y + q2.z*k2.z + q2.w*k2.w;
            float s3 = q3.x*k3.x + q3.y*k3.y + q3.z*k3.z + q3.w*k3.w;
            float s  = ((s0 + s1) + (s2 + s3)) * scale;

            float p;
            if (s > m) {
                float corr = __expf(m - s);
                l *= corr;
                o0.x*=corr; o0.y*=corr; o0.z*=corr; o0.w*=corr;
                o1.x*=corr; o1.y*=corr; o1.z*=corr; o1.w*=corr;
                o2.x*=corr; o2.y*=corr; o2.z*=corr; o2.w*=corr;
                o3.x*=corr; o3.y*=corr; o3.z*=corr; o3.w*=corr;
                m = s; p = 1.f;
            } else {
                p = __expf(s - m);
            }
            l += p;

            const float4* vr = (const float4*)&vs[j * D_];
            float4 v0 = vr[0], v1 = vr[1], v2 = vr[2], v3 = vr[3];
            o0.x = fmaf(p, v0.x, o0.x); o0.y = fmaf(p, v0.y, o0.y);
            o0.z = fmaf(p, v0.z, o0.z); o0.w = fmaf(p, v0.w, o0.w);
            o1.x = fmaf(p, v1.x, o1.x); o1.y = fmaf(p, v1.y, o1.y);
            o1.z = fmaf(p, v1.z, o1.z); o1.w = fmaf(p, v1.w, o1.w);
            o2.x = fmaf(p, v2.x, o2.x); o2.y = fmaf(p, v2.y, o2.y);
            o2.z = fmaf(p, v2.z, o2.z); o2.w = fmaf(p, v2.w, o2.w);
            o3.x = fmaf(p, v3.x, o3.x); o3.y = fmaf(p, v3.y, o3.y);
            o3.z = fmaf(p, v3.z, o3.z); o3.w = fmaf(p, v3.w, o3.w);
        }

        float inv = 1.f / l;
        float4* op = (float4*)&ao[base + (size_t)tid * C_];
        op[0] = make_float4(o0.x*inv, o0.y*inv, o0.z*inv, o0.w*inv);
        op[1] = make_float4(o1.x*inv, o1.y*inv, o1.z*inv, o1.w*inv);
        op[2] = make_float4(o2.x*inv, o2.y*inv, o2.z*inv, o2.w*inv);
        op[3] = make_float4(o3.x*inv, o3.y*inv, o3.z*inv, o3.w*inv);
    }
}

// ---------------------------------------------------------------------------
extern "C" void kernel_launch(void* const* d_in, const int* in_sizes, int n_in,
                              void* d_out, int out_size)
{
    const float* values = (const float*)d_in[0];
    const float* keys   = (const float*)d_in[1];
    const float* query  = (const float*)d_in[2];
    const float* Wv = (const float*)d_in[3];
    const float* bv = (const float*)d_in[4];
    const float* Wk = (const float*)d_in[5];
    const float* bk = (const float*)d_in[6];
    const float* Wq = (const float*)d_in[7];
    const float* bq = (const float*)d_in[8];
    const float* Wo = (const float*)d_in[9];
    const float* bo = (const float*)d_in[10];
    float* out = (float*)d_out;

    float *gq, *gk, *gv, *gao;
    cudaGetSymbolAddress((void**)&gq,  g_q);
    cudaGetSymbolAddress((void**)&gk,  g_k);
    cudaGetSymbolAddress((void**)&gv,  g_v);
    cudaGetSymbolAddress((void**)&gao, g_ao);

    const int gemm_smem = (GBM * APAD + C_ * APAD) * (int)sizeof(float); // 101376 B
    cudaFuncSetAttribute(gemm128, cudaFuncAttributeMaxDynamicSharedMemorySize, gemm_smem);

    dim3 gemm_grid(M_ / GBM);  // 1360

    // Projections
    gemm128<<<gemm_grid, 256, gemm_smem>>>(values, Wv, bv, gv);
    gemm128<<<gemm_grid, 256, gemm_smem>>>(keys,   Wk, bk, gk);
    gemm128<<<gemm_grid, 256, gemm_smem>>>(query,  Wq, bq, gq);

    // Attention
    dim3 attn_grid(BT_, H_);
    attn_kernel<<<attn_grid, 256>>>(gq, gk, gv, gao);

    // Output projection
    gemm128<<<gemm_grid, 256, gemm_smem>>>(gao, Wo, bo, out);
}

// round 4
// speedup vs baseline: 1.9251x; 1.9251x over previous
#include <cuda_runtime.h>
#include <math.h>
#include <cstdint>

// Problem constants (fixed by the reference)
#define B_  8
#define T_  64
#define N_  170
#define C_  128
#define H_  8
#define D_  16
#define BT_ (B_*T_)          // 512
#define M_  (BT_*N_)         // 87040 rows (multiple of 128)

// Scratch (allocation-free rule: __device__ globals)
__device__ float g_q [M_*C_];
__device__ float g_k [M_*C_];
__device__ float g_v [M_*C_];
__device__ float g_ao[M_*C_];

__device__ __forceinline__ uint32_t f2tf32(float x) {
    uint32_t r;
    asm("cvt.rna.tf32.f32 %0, %1;" : "=r"(r) : "f"(x));
    return r;
}

// ===========================================================================
// tf32 warp-MMA GEMM: out[M,128] = A[M,128] @ W^T + bias   (torch Linear)
// CTA = 128 rows x 128 cols, 256 threads (8 warps x 16 rows).
// A, W staged in smem as tf32 bits, PAD=132 floats/row (conflict-free frags).
// Each warp: 16 n-tiles (m16n8k8) x 16 k-steps, fp32 accum in registers.
// ===========================================================================
#define TCM 128
#define PAD 132

// smem byte offsets
#define SMO_BIAS 0          // 512 B
#define SMO_A    1024       // 128*132*4 = 67584 B (reused as fp32 epilogue stage)
#define SMO_W    (1024 + 67584)
#define SM_TOTAL (SMO_W + 67584)   // 136192 B

__global__ __launch_bounds__(256, 1)
void gemm_mma(const float* __restrict__ A, const float* __restrict__ W,
              const float* __restrict__ bias, float* __restrict__ out)
{
    extern __shared__ char smraw[];
    uint32_t* As = (uint32_t*)(smraw + SMO_A);
    uint32_t* Ws = (uint32_t*)(smraw + SMO_W);
    float*    sb = (float*)(smraw + SMO_BIAS);

    const int tid = threadIdx.x;
    const int wid = tid >> 5;
    const int lid = tid & 31;
    const int ly  = lid >> 2;      // 0..7
    const int lx  = lid & 3;       // 0..3
    const size_t row0 = (size_t)blockIdx.x * TCM;

    if (tid < C_) sb[tid] = bias[tid];

    // ---- Stage A tile and W into smem, converting to tf32 ----
    {
        const float4* Ag = (const float4*)(A + row0 * C_);
        const float4* Wg = (const float4*)W;
        #pragma unroll
        for (int i = 0; i < 16; i++) {
            int idx = tid + i * 256;          // 0..4095
            int r   = idx >> 5;               // row 0..127
            int c4  = idx & 31;               // float4 col
            float4 va = Ag[idx];
            float4 vw = Wg[idx];
            uint4 ua = make_uint4(f2tf32(va.x), f2tf32(va.y), f2tf32(va.z), f2tf32(va.w));
            uint4 uw = make_uint4(f2tf32(vw.x), f2tf32(vw.y), f2tf32(vw.z), f2tf32(vw.w));
            *(uint4*)&As[r * PAD + c4 * 4] = ua;
            *(uint4*)&Ws[r * PAD + c4 * 4] = uw;
        }
    }
    __syncthreads();

    // ---- MMA mainloop ----
    float acc[16][4];
    #pragma unroll
    for (int nt = 0; nt < 16; nt++)
        #pragma unroll
        for (int c = 0; c < 4; c++) acc[nt][c] = 0.f;

    const uint32_t* Aw = As + (wid * 16) * PAD;

    #pragma unroll 4
    for (int ks = 0; ks < 16; ks++) {
        const int k0 = ks * 8;
        uint32_t a0 = Aw[(ly    ) * PAD + k0 + lx    ];
        uint32_t a1 = Aw[(ly + 8) * PAD + k0 + lx    ];
        uint32_t a2 = Aw[(ly    ) * PAD + k0 + lx + 4];
        uint32_t a3 = Aw[(ly + 8) * PAD + k0 + lx + 4];
        #pragma unroll
        for (int nt = 0; nt < 16; nt++) {
            uint32_t b0 = Ws[(nt * 8 + ly) * PAD + k0 + lx    ];
            uint32_t b1 = Ws[(nt * 8 + ly) * PAD + k0 + lx + 4];
            asm volatile(
                "mma.sync.aligned.m16n8k8.row.col.f32.tf32.tf32.f32 "
                "{%0,%1,%2,%3}, {%4,%5,%6,%7}, {%8,%9}, {%0,%1,%2,%3};"
                : "+f"(acc[nt][0]), "+f"(acc[nt][1]),
                  "+f"(acc[nt][2]), "+f"(acc[nt][3])
                : "r"(a0), "r"(a1), "r"(a2), "r"(a3), "r"(b0), "r"(b1));
        }
    }
    __syncthreads();   // done reading As; reuse as epilogue stage

    // ---- Stage accumulators to smem (fp32), rows wid*16.. ----
    {
        float* stg = (float*)(smraw + SMO_A);
        const int r0 = wid * 16 + ly;
        #pragma unroll
        for (int nt = 0; nt < 16; nt++) {
            int cc = nt * 8 + lx * 2;
            *(float2*)&stg[(r0    ) * PAD + cc] = make_float2(acc[nt][0], acc[nt][1]);
            *(float2*)&stg[(r0 + 8) * PAD + cc] = make_float2(acc[nt][2], acc[nt][3]);
        }
    }
    __syncthreads();

    // ---- Coalesced global store with bias ----
    {
        const float*  stg = (const float*)(smraw + SMO_A);
        const float4* sb4 = (const float4*)sb;
        #pragma unroll
        for (int i = 0; i < 16; i++) {
            int idx = tid + i * 256;
            int r   = idx >> 5;
            int c4  = idx & 31;
            float4 v = *(const float4*)&stg[r * PAD + c4 * 4];
            float4 b = sb4[c4];
            v.x += b.x; v.y += b.y; v.z += b.z; v.w += b.w;
            *(float4*)&out[(row0 + r) * C_ + c4 * 4] = v;
        }
    }
}

// ---------------------------------------------------------------------------
// Attention: one block per (bt, head-pair). K,V tiles for 2 heads (170x32,
// contiguous columns) staged in smem. 384 threads; threads 0-169 -> head 0,
// 192-361 -> head 1 (warp-aligned). Online softmax, FP32.
// ---------------------------------------------------------------------------
__global__ __launch_bounds__(384)
void attn_kernel(const float* __restrict__ q, const float* __restrict__ k,
                 const float* __restrict__ v, float* __restrict__ ao)
{
    __shared__ float ks[N_ * 32];   // 21760 B
    __shared__ float vs[N_ * 32];

    const int bt  = blockIdx.x;
    const int hp  = blockIdx.y;          // head pair 0..3
    const int tid = threadIdx.x;
    const size_t base = (size_t)bt * N_ * C_ + hp * 32;

    // load both heads' K,V (32 contiguous floats per row)
    for (int idx4 = tid; idx4 < N_ * 8; idx4 += 384) {
        int n = idx4 >> 3, d4 = idx4 & 7;
        *(float4*)&ks[n * 32 + d4 * 4] = *(const float4*)&k[base + (size_t)n * C_ + d4 * 4];
        *(float4*)&vs[n * 32 + d4 * 4] = *(const float4*)&v[base + (size_t)n * C_ + d4 * 4];
    }
    __syncthreads();

    const int h  = (tid >= 192) ? 1 : 0;
    const int qi = tid - 192 * h;
    if (qi < N_) {
        const int hoff = h * 16;
        const float4* qp = (const float4*)&q[base + (size_t)qi * C_ + hoff];
        float4 q0 = qp[0], q1 = qp[1], q2 = qp[2], q3 = qp[3];

        const float scale = 0.08838834764831845f;   // 1/sqrt(128)
        float m = -1e30f, l = 0.f;
        float4 o0 = make_float4(0,0,0,0), o1 = o0, o2 = o0, o3 = o0;

        for (int j = 0; j < N_; j++) {
            const float4* kr = (const float4*)&ks[j * 32 + hoff];
            float4 k0 = kr[0], k1 = kr[1], k2 = kr[2], k3 = kr[3];
            float s0 = q0.x*k0.x + q0.y*k0.y + q0.z*k0.z + q0.w*k0.w;
            float s1 = q1.x*k1.x + q1.y*k1.y + q1.z*k1.z + q1.w*k1.w;
            float s2 = q2.x*k2.x + q2.y*k2.y + q2.z*k2.z + q2.w*k2.w;
            float s3 = q3.x*k3.x + q3.y*k3.y + q3.z*k3.z + q3.w*k3.w;
            float s  = ((s0 + s1) + (s2 + s3)) * scale;

            float p;
            if (s > m) {
                float corr = __expf(m - s);
                l *= corr;
                o0.x*=corr; o0.y*=corr; o0.z*=corr; o0.w*=corr;
                o1.x*=corr; o1.y*=corr; o1.z*=corr; o1.w*=corr;
                o2.x*=corr; o2.y*=corr; o2.z*=corr; o2.w*=corr;
                o3.x*=corr; o3.y*=corr; o3.z*=corr; o3.w*=corr;
                m = s; p = 1.f;
            } else {
                p = __expf(s - m);
            }
            l += p;

            const float4* vr = (const float4*)&vs[j * 32 + hoff];
            float4 v0 = vr[0], v1 = vr[1], v2 = vr[2], v3 = vr[3];
            o0.x = fmaf(p, v0.x, o0.x); o0.y = fmaf(p, v0.y, o0.y);
            o0.z = fmaf(p, v0.z, o0.z); o0.w = fmaf(p, v0.w, o0.w);
            o1.x = fmaf(p, v1.x, o1.x); o1.y = fmaf(p, v1.y, o1.y);
            o1.z = fmaf(p, v1.z, o1.z); o1.w = fmaf(p, v1.w, o1.w);
            o2.x = fmaf(p, v2.x, o2.x); o2.y = fmaf(p, v2.y, o2.y);
            o2.z = fmaf(p, v2.z, o2.z); o2.w = fmaf(p, v2.w, o2.w);
            o3.x = fmaf(p, v3.x, o3.x); o3.y = fmaf(p, v3.y, o3.y);
            o3.z = fmaf(p, v3.z, o3.z); o3.w = fmaf(p, v3.w, o3.w);
        }

        float inv = 1.f / l;
        float4* op = (float4*)&ao[base + (size_t)qi * C_ + hoff];
        op[0] = make_float4(o0.x*inv, o0.y*inv, o0.z*inv, o0.w*inv);
        op[1] = make_float4(o1.x*inv, o1.y*inv, o1.z*inv, o1.w*inv);
        op[2] = make_float4(o2.x*inv, o2.y*inv, o2.z*inv, o2.w*inv);
        op[3] = make_float4(o3.x*inv, o3.y*inv, o3.z*inv, o3.w*inv);
    }
}

// ---------------------------------------------------------------------------
extern "C" void kernel_launch(void* const* d_in, const int* in_sizes, int n_in,
                              void* d_out, int out_size)
{
    const float* values = (const float*)d_in[0];
    const float* keys   = (const float*)d_in[1];
    const float* query  = (const float*)d_in[2];
    const float* Wv = (const float*)d_in[3];
    const float* bv = (const float*)d_in[4];
    const float* Wk = (const float*)d_in[5];
    const float* bk = (const float*)d_in[6];
    const float* Wq = (const float*)d_in[7];
    const float* bq = (const float*)d_in[8];
    const float* Wo = (const float*)d_in[9];
    const float* bo = (const float*)d_in[10];
    float* out = (float*)d_out;

    float *gq, *gk, *gv, *gao;
    cudaGetSymbolAddress((void**)&gq,  g_q);
    cudaGetSymbolAddress((void**)&gk,  g_k);
    cudaGetSymbolAddress((void**)&gv,  g_v);
    cudaGetSymbolAddress((void**)&gao, g_ao);

    cudaFuncSetAttribute(gemm_mma, cudaFuncAttributeMaxDynamicSharedMemorySize, SM_TOTAL);

    dim3 gemm_grid(M_ / TCM);   // 680

    gemm_mma<<<gemm_grid, 256, SM_TOTAL>>>(values, Wv, bv, gv);
    gemm_mma<<<gemm_grid, 256, SM_TOTAL>>>(keys,   Wk, bk, gk);
    gemm_mma<<<gemm_grid, 256, SM_TOTAL>>>(query,  Wq, bq, gq);

    dim3 attn_grid(BT_, H_ / 2);
    attn_kernel<<<attn_grid, 384>>>(gq, gk, gv, gao);

    gemm_mma<<<gemm_grid, 256, SM_TOTAL>>>(gao, Wo, bo, out);
}

// round 5
// speedup vs baseline: 3.1255x; 1.6235x over previous
#include <cuda_runtime.h>
#include <math.h>
#include <cstdint>

// Problem constants (fixed by the reference)
#define B_  8
#define T_  64
#define N_  170
#define C_  128
#define H_  8
#define D_  16
#define BT_ (B_*T_)          // 512
#define M_  (BT_*N_)         // 87040 rows (multiple of 128)

// Scratch (allocation-free rule: __device__ globals)
__device__ float g_q [M_*C_];
__device__ float g_k [M_*C_];
__device__ float g_v [M_*C_];
__device__ float g_ao[M_*C_];

__device__ __forceinline__ uint32_t f2tf32(float x) {
    uint32_t r;
    asm("cvt.rna.tf32.f32 %0, %1;" : "=r"(r) : "f"(x));
    return r;
}

__device__ __forceinline__ void mma_tf32(float* d, const uint32_t* a,
                                         uint32_t b0, uint32_t b1) {
    asm volatile(
        "mma.sync.aligned.m16n8k8.row.col.f32.tf32.tf32.f32 "
        "{%0,%1,%2,%3}, {%4,%5,%6,%7}, {%8,%9}, {%0,%1,%2,%3};"
        : "+f"(d[0]), "+f"(d[1]), "+f"(d[2]), "+f"(d[3])
        : "r"(a[0]), "r"(a[1]), "r"(a[2]), "r"(a[3]), "r"(b0), "r"(b1));
}

// ===========================================================================
// tf32 warp-MMA GEMM: out[M,128] = A[M,128] @ W^T + bias  (unchanged from R4)
// ===========================================================================
#define TCM 128
#define PAD 132

#define SMO_BIAS 0
#define SMO_A    1024
#define SMO_W    (1024 + 67584)
#define SM_TOTAL (SMO_W + 67584)   // 136192 B

__global__ __launch_bounds__(256, 1)
void gemm_mma(const float* __restrict__ A, const float* __restrict__ W,
              const float* __restrict__ bias, float* __restrict__ out)
{
    extern __shared__ char smraw[];
    uint32_t* As = (uint32_t*)(smraw + SMO_A);
    uint32_t* Ws = (uint32_t*)(smraw + SMO_W);
    float*    sb = (float*)(smraw + SMO_BIAS);

    const int tid = threadIdx.x;
    const int wid = tid >> 5;
    const int lid = tid & 31;
    const int ly  = lid >> 2;
    const int lx  = lid & 3;
    const size_t row0 = (size_t)blockIdx.x * TCM;

    if (tid < C_) sb[tid] = bias[tid];

    {
        const float4* Ag = (const float4*)(A + row0 * C_);
        const float4* Wg = (const float4*)W;
        #pragma unroll
        for (int i = 0; i < 16; i++) {
            int idx = tid + i * 256;
            int r   = idx >> 5;
            int c4  = idx & 31;
            float4 va = Ag[idx];
            float4 vw = Wg[idx];
            uint4 ua = make_uint4(f2tf32(va.x), f2tf32(va.y), f2tf32(va.z), f2tf32(va.w));
            uint4 uw = make_uint4(f2tf32(vw.x), f2tf32(vw.y), f2tf32(vw.z), f2tf32(vw.w));
            *(uint4*)&As[r * PAD + c4 * 4] = ua;
            *(uint4*)&Ws[r * PAD + c4 * 4] = uw;
        }
    }
    __syncthreads();

    float acc[16][4];
    #pragma unroll
    for (int nt = 0; nt < 16; nt++)
        #pragma unroll
        for (int c = 0; c < 4; c++) acc[nt][c] = 0.f;

    const uint32_t* Aw = As + (wid * 16) * PAD;

    #pragma unroll 4
    for (int ks = 0; ks < 16; ks++) {
        const int k0 = ks * 8;
        uint32_t a[4];
        a[0] = Aw[(ly    ) * PAD + k0 + lx    ];
        a[1] = Aw[(ly + 8) * PAD + k0 + lx    ];
        a[2] = Aw[(ly    ) * PAD + k0 + lx + 4];
        a[3] = Aw[(ly + 8) * PAD + k0 + lx + 4];
        #pragma unroll
        for (int nt = 0; nt < 16; nt++) {
            uint32_t b0 = Ws[(nt * 8 + ly) * PAD + k0 + lx    ];
            uint32_t b1 = Ws[(nt * 8 + ly) * PAD + k0 + lx + 4];
            mma_tf32(acc[nt], a, b0, b1);
        }
    }
    __syncthreads();

    {
        float* stg = (float*)(smraw + SMO_A);
        const int r0 = wid * 16 + ly;
        #pragma unroll
        for (int nt = 0; nt < 16; nt++) {
            int cc = nt * 8 + lx * 2;
            *(float2*)&stg[(r0    ) * PAD + cc] = make_float2(acc[nt][0], acc[nt][1]);
            *(float2*)&stg[(r0 + 8) * PAD + cc] = make_float2(acc[nt][2], acc[nt][3]);
        }
    }
    __syncthreads();

    {
        const float*  stg = (const float*)(smraw + SMO_A);
        const float4* sb4 = (const float4*)sb;
        #pragma unroll
        for (int i = 0; i < 16; i++) {
            int idx = tid + i * 256;
            int r   = idx >> 5;
            int c4  = idx & 31;
            float4 v = *(const float4*)&stg[r * PAD + c4 * 4];
            float4 b = sb4[c4];
            v.x += b.x; v.y += b.y; v.z += b.z; v.w += b.w;
            *(float4*)&out[(row0 + r) * C_ + c4 * 4] = v;
        }
    }
}

// ===========================================================================
// Tensor-core flash attention. One CTA per (bt, h). 352 threads = 11 warps.
// Warp w owns query m-tile rows [16w, 16w+16). Keys processed in 6 chunks
// of 32 (N padded 170 -> 192 with zeros; masked at p).
// Q/K smem stride 20, V stride 24, P stage stride 36 (frag-conflict-free).
// ===========================================================================
#define QKS 20
#define VVS 24
#define PPS 36
#define QW  (176 * QKS)          // 3520 words
#define KW  (192 * QKS)          // 3840
#define VW  (192 * VVS)          // 4608
#define PW  (16 * PPS)           // 576 per warp
#define ATT_WORDS (QW + KW + VW + 11 * PW)     // 18304
#define ATT_SMEM  (ATT_WORDS * 4)              // 73216 B

__global__ __launch_bounds__(352)
void attn_mma(const float* __restrict__ q, const float* __restrict__ k,
              const float* __restrict__ v, float* __restrict__ ao)
{
    extern __shared__ float sa[];
    float* Qs = sa;
    float* Ks = Qs + QW;
    float* Vs = Ks + KW;
    float* Pb = Vs + VW;

    const int bt  = blockIdx.x;
    const int h   = blockIdx.y;
    const int tid = threadIdx.x;
    const int wid = tid >> 5;          // 0..10  (= query m-tile)
    const int lid = tid & 31;
    const int g   = lid >> 2;          // 0..7
    const int t   = lid & 3;           // 0..3
    const size_t base = (size_t)bt * (N_ * C_) + h * D_;

    // zero Q/K/V buffers (covers pad rows)
    for (int i = tid; i < QW + KW + VW; i += 352) sa[i] = 0.f;
    __syncthreads();

    // stage Q, K, V head tiles as tf32 (rows 0..169, 16 cols each)
    for (int idx = tid; idx < N_ * 4; idx += 352) {
        int r  = idx >> 2;
        int c4 = (idx & 3) * 4;
        float4 qv = *(const float4*)&q[base + (size_t)r * C_ + c4];
        float4 kv = *(const float4*)&k[base + (size_t)r * C_ + c4];
        float4 vv = *(const float4*)&v[base + (size_t)r * C_ + c4];
        uint32_t* dq = (uint32_t*)(Qs + r * QKS + c4);
        uint32_t* dk = (uint32_t*)(Ks + r * QKS + c4);
        uint32_t* dv = (uint32_t*)(Vs + r * VVS + c4);
        dq[0] = f2tf32(qv.x); dq[1] = f2tf32(qv.y); dq[2] = f2tf32(qv.z); dq[3] = f2tf32(qv.w);
        dk[0] = f2tf32(kv.x); dk[1] = f2tf32(kv.y); dk[2] = f2tf32(kv.z); dk[3] = f2tf32(kv.w);
        dv[0] = f2tf32(vv.x); dv[1] = f2tf32(vv.y); dv[2] = f2tf32(vv.z); dv[3] = f2tf32(vv.w);
    }
    __syncthreads();

    float* Pw = Pb + wid * PW;
    const uint32_t* Qu = (const uint32_t*)Qs;
    const uint32_t* Ku = (const uint32_t*)Ks;
    const uint32_t* Vu = (const uint32_t*)Vs;
    uint32_t* Pu = (uint32_t*)Pw;

    // Q A-frags for full k=16 (loop invariant)
    uint32_t qa[8];
    {
        const int r0 = wid * 16;
        qa[0] = Qu[(r0 + g    ) * QKS + t     ];
        qa[1] = Qu[(r0 + g + 8) * QKS + t     ];
        qa[2] = Qu[(r0 + g    ) * QKS + t + 4 ];
        qa[3] = Qu[(r0 + g + 8) * QKS + t + 4 ];
        qa[4] = Qu[(r0 + g    ) * QKS + t + 8 ];
        qa[5] = Qu[(r0 + g + 8) * QKS + t + 8 ];
        qa[6] = Qu[(r0 + g    ) * QKS + t + 12];
        qa[7] = Qu[(r0 + g + 8) * QKS + t + 12];
    }

    const float scale = 0.08838834764831845f;   // 1/sqrt(128)
    float m0 = -1e30f, m1 = -1e30f, l0 = 0.f, l1 = 0.f;
    float oa[2][4];
    #pragma unroll
    for (int nt = 0; nt < 2; nt++)
        #pragma unroll
        for (int c = 0; c < 4; c++) oa[nt][c] = 0.f;

    for (int ch = 0; ch < 6; ch++) {
        // ---- S chunk: 4 n-tiles of 8 keys ----
        float sacc[4][4];
        #pragma unroll
        for (int j = 0; j < 4; j++)
            #pragma unroll
            for (int c = 0; c < 4; c++) sacc[j][c] = 0.f;

        #pragma unroll
        for (int j = 0; j < 4; j++) {
            const int n0 = ch * 32 + j * 8;
            uint32_t b0 = Ku[(n0 + g) * QKS + t     ];
            uint32_t b1 = Ku[(n0 + g) * QKS + t + 4 ];
            mma_tf32(sacc[j], qa, b0, b1);
            uint32_t b2 = Ku[(n0 + g) * QKS + t + 8 ];
            uint32_t b3 = Ku[(n0 + g) * QKS + t + 12];
            mma_tf32(sacc[j], qa + 4, b2, b3);
        }

        // ---- online softmax update ----
        float cm0 = sacc[0][0], cm1 = sacc[0][2];
        #pragma unroll
        for (int j = 0; j < 4; j++) {
            cm0 = fmaxf(cm0, fmaxf(sacc[j][0], sacc[j][1]));
            cm1 = fmaxf(cm1, fmaxf(sacc[j][2], sacc[j][3]));
        }
        cm0 = fmaxf(cm0, __shfl_xor_sync(0xFFFFFFFF, cm0, 1));
        cm0 = fmaxf(cm0, __shfl_xor_sync(0xFFFFFFFF, cm0, 2));
        cm1 = fmaxf(cm1, __shfl_xor_sync(0xFFFFFFFF, cm1, 1));
        cm1 = fmaxf(cm1, __shfl_xor_sync(0xFFFFFFFF, cm1, 2));

        float mn0 = fmaxf(m0, cm0 * scale);
        float mn1 = fmaxf(m1, cm1 * scale);
        float cr0 = __expf(m0 - mn0);
        float cr1 = __expf(m1 - mn1);
        m0 = mn0; m1 = mn1;
        l0 *= cr0; l1 *= cr1;
        #pragma unroll
        for (int nt = 0; nt < 2; nt++) {
            oa[nt][0] *= cr0; oa[nt][1] *= cr0;
            oa[nt][2] *= cr1; oa[nt][3] *= cr1;
        }

        // ---- p = exp(s*scale - m), mask pad cols, stage to smem as tf32 ----
        #pragma unroll
        for (int j = 0; j < 4; j++) {
            const int cb   = ch * 32 + j * 8;
            const int col0 = cb + 2 * t;
            const int col1 = col0 + 1;
            float p00 = (col0 < N_) ? __expf(fmaf(sacc[j][0], scale, -m0)) : 0.f;
            float p01 = (col1 < N_) ? __expf(fmaf(sacc[j][1], scale, -m0)) : 0.f;
            float p10 = (col0 < N_) ? __expf(fmaf(sacc[j][2], scale, -m1)) : 0.f;
            float p11 = (col1 < N_) ? __expf(fmaf(sacc[j][3], scale, -m1)) : 0.f;
            l0 += p00 + p01;
            l1 += p10 + p11;
            uint32_t* d0 = Pu + (g    ) * PPS + j * 8 + 2 * t;
            uint32_t* d1 = Pu + (g + 8) * PPS + j * 8 + 2 * t;
            d0[0] = f2tf32(p00); d0[1] = f2tf32(p01);
            d1[0] = f2tf32(p10); d1[1] = f2tf32(p11);
        }
        __syncwarp();

        // ---- O += P @ V (4 ksteps x 2 n-tiles) ----
        #pragma unroll
        for (int kk = 0; kk < 4; kk++) {
            uint32_t pa[4];
            pa[0] = Pu[(g    ) * PPS + kk * 8 + t    ];
            pa[1] = Pu[(g + 8) * PPS + kk * 8 + t    ];
            pa[2] = Pu[(g    ) * PPS + kk * 8 + t + 4];
            pa[3] = Pu[(g + 8) * PPS + kk * 8 + t + 4];
            const int k0 = ch * 32 + kk * 8;
            #pragma unroll
            for (int nt = 0; nt < 2; nt++) {
                uint32_t vb0 = Vu[(k0 + t    ) * VVS + nt * 8 + g];
                uint32_t vb1 = Vu[(k0 + t + 4) * VVS + nt * 8 + g];
                mma_tf32(oa[nt], pa, vb0, vb1);
            }
        }
        __syncwarp();
    }

    // ---- finalize: row sums across quad, normalize, store ----
    l0 += __shfl_xor_sync(0xFFFFFFFF, l0, 1);
    l0 += __shfl_xor_sync(0xFFFFFFFF, l0, 2);
    l1 += __shfl_xor_sync(0xFFFFFFFF, l1, 1);
    l1 += __shfl_xor_sync(0xFFFFFFFF, l1, 2);
    const float i0 = 1.f / l0;
    const float i1 = 1.f / l1;

    const int r0 = wid * 16 + g;
    const int r1 = r0 + 8;
    if (r0 < N_) {
        #pragma unroll
        for (int nt = 0; nt < 2; nt++)
            *(float2*)&ao[base + (size_t)r0 * C_ + nt * 8 + 2 * t] =
                make_float2(oa[nt][0] * i0, oa[nt][1] * i0);
    }
    if (r1 < N_) {
        #pragma unroll
        for (int nt = 0; nt < 2; nt++)
            *(float2*)&ao[base + (size_t)r1 * C_ + nt * 8 + 2 * t] =
                make_float2(oa[nt][2] * i1, oa[nt][3] * i1);
    }
}

// ---------------------------------------------------------------------------
extern "C" void kernel_launch(void* const* d_in, const int* in_sizes, int n_in,
                              void* d_out, int out_size)
{
    const float* values = (const float*)d_in[0];
    const float* keys   = (const float*)d_in[1];
    const float* query  = (const float*)d_in[2];
    const float* Wv = (const float*)d_in[3];
    const float* bv = (const float*)d_in[4];
    const float* Wk = (const float*)d_in[5];
    const float* bk = (const float*)d_in[6];
    const float* Wq = (const float*)d_in[7];
    const float* bq = (const float*)d_in[8];
    const float* Wo = (const float*)d_in[9];
    const float* bo = (const float*)d_in[10];
    float* out = (float*)d_out;

    float *gq, *gk, *gv, *gao;
    cudaGetSymbolAddress((void**)&gq,  g_q);
    cudaGetSymbolAddress((void**)&gk,  g_k);
    cudaGetSymbolAddress((void**)&gv,  g_v);
    cudaGetSymbolAddress((void**)&gao, g_ao);

    cudaFuncSetAttribute(gemm_mma, cudaFuncAttributeMaxDynamicSharedMemorySize, SM_TOTAL);
    cudaFuncSetAttribute(attn_mma, cudaFuncAttributeMaxDynamicSharedMemorySize, ATT_SMEM);

    dim3 gemm_grid(M_ / TCM);   // 680

    gemm_mma<<<gemm_grid, 256, SM_TOTAL>>>(values, Wv, bv, gv);
    gemm_mma<<<gemm_grid, 256, SM_TOTAL>>>(keys,   Wk, bk, gk);
    gemm_mma<<<gemm_grid, 256, SM_TOTAL>>>(query,  Wq, bq, gq);

    dim3 attn_grid(BT_, H_);
    attn_mma<<<attn_grid, 352, ATT_SMEM>>>(gq, gk, gv, gao);

    gemm_mma<<<gemm_grid, 256, SM_TOTAL>>>(gao, Wo, bo, out);
}